// round 2
// baseline (speedup 1.0000x reference)
#include <cuda_runtime.h>
#include <cstdint>

#define N_QUBITS 16
#define DIM 65536
#define BATCH 128

// Scratch state buffers (device globals: allocation-free rule).
__device__ float2 g_state0[BATCH * DIM];
__device__ float2 g_state1[BATCH * DIM];
__device__ float  g_partial[BATCH * 16 * 16];   // [b][loGroup][q]

// ---------------------------------------------------------------------------
// CNOT-ring permutation sigma: new index j from old index i.
// b[p] = XOR(a[p..15]) for p<15 ; b[15] = XOR(a[0..14]).
__device__ __forceinline__ int sigma16(int i) {
    int t = i;
    t ^= t >> 1; t ^= t >> 2; t ^= t >> 4; t ^= t >> 8;
    int b15 = (t ^ (i >> 15)) & 1;
    return (t & 0x7FFF) | (b15 << 15);
}

// ---------------------------------------------------------------------------
// Gate construction: G = Rot(phi,theta,omega) @ RY(x)   (complex 2x2)
// layout g[8] = {G00r,G00i, G01r,G01i, G10r,G10i, G11r,G11i}
__device__ void compute_gate(const float* __restrict__ x,
                             const float* __restrict__ w,
                             int b, int l, int q, float g[8]) {
    float xv  = x[(b * 4 + l) * 16 + q];
    const float* wp = w + (l * 16 + q) * 3;
    float phi = wp[0], th = wp[1], om = wp[2];
    float ct, st, cr, sr, sp, cp, sm, cm;
    sincosf(0.5f * th, &st, &ct);
    sincosf(0.5f * xv, &sr, &cr);
    sincosf(0.5f * (phi + om), &sp, &cp);
    sincosf(0.5f * (phi - om), &sm, &cm);
    // m00 = e^{-i(phi+om)/2} c ; m01 = -conj(e^{-i(phi-om)/2}) s
    // m10 = e^{-i(phi-om)/2} s ; m11 = conj(e^{-i(phi+om)/2}) c
    float m00r =  cp * ct, m00i = -sp * ct;
    float m01r = -cm * st, m01i = -sm * st;
    float m10r =  cm * st, m10i = -sm * st;
    float m11r =  cp * ct, m11i =  sp * ct;
    // G = m @ [[cr,-sr],[sr,cr]]
    g[0] =  m00r * cr + m01r * sr;  g[1] =  m00i * cr + m01i * sr;   // G00
    g[2] = -m00r * sr + m01r * cr;  g[3] = -m00i * sr + m01i * cr;   // G01
    g[4] =  m10r * cr + m11r * sr;  g[5] =  m10i * cr + m11i * sr;   // G10
    g[6] = -m10r * sr + m11r * cr;  g[7] = -m10i * sr + m11i * cr;   // G11
}

// (A,B) <- G (A,B)
__device__ __forceinline__ void cgate(float2& A, float2& B, const float* __restrict__ g) {
    float ar = A.x, ai = A.y, br = B.x, bi = B.y;
    A.x = g[0]*ar - g[1]*ai + g[2]*br - g[3]*bi;
    A.y = g[0]*ai + g[1]*ar + g[2]*bi + g[3]*br;
    B.x = g[4]*ar - g[5]*ai + g[6]*br - g[7]*bi;
    B.y = g[4]*ai + g[5]*ar + g[6]*bi + g[7]*br;
}

// Apply 8 gates to 256 amplitudes distributed as:
//   lane bits 0..4 -> local bits 0..4 (gates g[0..4], shfl butterflies)
//   reg index r bits 0..2 -> local bits 5..7 (gates g[5..7], in registers)
__device__ __forceinline__ void apply8(float2 v[8], const float (*g)[8], int lane) {
    #pragma unroll
    for (int pb = 0; pb < 3; pb++) {
        int m = 1 << pb;
        #pragma unroll
        for (int r = 0; r < 8; r++)
            if (!(r & m)) cgate(v[r], v[r + m], g[5 + pb]);
    }
    #pragma unroll
    for (int p = 0; p < 5; p++) {
        const float* gg = g[p];
        int bit = (lane >> p) & 1;
        float c0r = bit ? gg[6] : gg[0];   // coeff of own element
        float c0i = bit ? gg[7] : gg[1];
        float c1r = bit ? gg[4] : gg[2];   // coeff of partner element
        float c1i = bit ? gg[5] : gg[3];
        #pragma unroll
        for (int r = 0; r < 8; r++) {
            float pr = __shfl_xor_sync(0xffffffffu, v[r].x, 1 << p);
            float pi = __shfl_xor_sync(0xffffffffu, v[r].y, 1 << p);
            float nr = c0r * v[r].x - c0i * v[r].y + c1r * pr - c1i * pi;
            float ni = c0r * v[r].y + c0i * v[r].x + c1r * pi + c1i * pr;
            v[r].x = nr; v[r].y = ni;
        }
    }
}

// ---------------------------------------------------------------------------
// K1: layer 0 from |0>: product state, then CNOT-ring scatter. Write-only.
__global__ __launch_bounds__(256)
void k_init(const float* __restrict__ x, const float* __restrict__ w,
            float2* __restrict__ st) {
    int b = blockIdx.x, tid = threadIdx.x;
    __shared__ float  gcol[16][4];           // (G00, G10) per index bit
    __shared__ float2 loP[256], hiP[256];
    if (tid < 16) {
        float g[8];
        int p = tid;           // index bit
        int q = 15 - p;        // qubit
        compute_gate(x, w, b, 0, q, g);
        gcol[p][0] = g[0]; gcol[p][1] = g[1];
        gcol[p][2] = g[4]; gcol[p][3] = g[5];
    }
    __syncthreads();
    {
        float lr = 1.f, li = 0.f, hr = 1.f, hi = 0.f;
        #pragma unroll
        for (int p = 0; p < 8; p++) {
            int bit = (tid >> p) & 1;
            float ar = gcol[p][2 * bit], ai = gcol[p][2 * bit + 1];
            float nr = lr * ar - li * ai, ni = lr * ai + li * ar;
            lr = nr; li = ni;
            float br = gcol[p + 8][2 * bit], bi = gcol[p + 8][2 * bit + 1];
            nr = hr * br - hi * bi; ni = hr * bi + hi * br;
            hr = nr; hi = ni;
        }
        loP[tid] = make_float2(lr, li);
        hiP[tid] = make_float2(hr, hi);
    }
    __syncthreads();
    float2* base = st + (size_t)b * DIM;
    for (int it = 0; it < 256; it++) {
        int i = it * 256 + tid;
        float2 h = hiP[it], lo = loP[tid];
        float2 amp = make_float2(h.x * lo.x - h.y * lo.y,
                                 h.x * lo.y + h.y * lo.x);
        base[sigma16(i)] = amp;
    }
}

// ---------------------------------------------------------------------------
// KA: gates on index bits 0..7 (qubits 15..8). In-place, warp-local, no smem tile.
__global__ __launch_bounds__(256)
void k_low(const float* __restrict__ x, const float* __restrict__ w,
           int layer, float2* __restrict__ st) {
    int b = blockIdx.y, tid = threadIdx.x;
    int wid = tid >> 5, lane = tid & 31;
    __shared__ float g[8][8];
    if (tid < 8) {
        float gg[8];
        compute_gate(x, w, b, layer, 15 - tid, gg);
        #pragma unroll
        for (int k = 0; k < 8; k++) g[tid][k] = gg[k];
    }
    __syncthreads();
    int hi = blockIdx.x * 8 + wid;                     // 0..255
    float2* base = st + (size_t)b * DIM + hi * 256;
    float2 v[8];
    #pragma unroll
    for (int r = 0; r < 8; r++) v[r] = base[r * 32 + lane];
    apply8(v, g, lane);
    #pragma unroll
    for (int r = 0; r < 8; r++) base[r * 32 + lane] = v[r];
}

// ---------------------------------------------------------------------------
// KB: gates on index bits 8..15 (qubits 7..0) via smem transpose tile,
// fused CNOT-ring scatter (non-final) or fused sign-weighted reduction (final).
template <bool FINAL>
__global__ __launch_bounds__(256)
void k_high(const float* __restrict__ x, const float* __restrict__ w,
            int layer, const float2* __restrict__ in,
            float2* __restrict__ outst, float* __restrict__ part) {
    int b = blockIdx.y, logrp = blockIdx.x;            // lo group (16 lo each)
    int tid = threadIdx.x, wid = tid >> 5, lane = tid & 31;
    __shared__ float  g[8][8];
    __shared__ float2 tile[16][257];                   // [lo][hi] padded
    __shared__ float  wsum[8][16];

    if (tid < 8) {
        float gg[8];
        compute_gate(x, w, b, layer, 7 - tid, gg);     // bit p+8 -> qubit 7-p
        #pragma unroll
        for (int k = 0; k < 8; k++) g[tid][k] = gg[k];
    }
    __syncthreads();

    const float2* ibase = in + (size_t)b * DIM + logrp * 16;
    // Load: coalesced global -> transposed smem
    #pragma unroll 4
    for (int it = 0; it < 16; it++) {
        int hi = it * 16 + wid * 2 + (lane >> 4);
        int lo = lane & 15;
        tile[lo][hi] = ibase[hi * 256 + lo];
    }
    __syncthreads();

    // Gate phase along hi: warp handles 2 lo columns
    #pragma unroll
    for (int sub = 0; sub < 2; sub++) {
        int lo = wid * 2 + sub;
        float2 v[8];
        #pragma unroll
        for (int r = 0; r < 8; r++) v[r] = tile[lo][r * 32 + lane];
        apply8(v, g, lane);
        #pragma unroll
        for (int r = 0; r < 8; r++) tile[lo][r * 32 + lane] = v[r];
    }
    __syncthreads();

    if (!FINAL) {
        float2* obase = outst + (size_t)b * DIM;
        #pragma unroll 4
        for (int it = 0; it < 16; it++) {
            int hi = it * 16 + wid * 2 + (lane >> 4);
            int lo = lane & 15;
            float2 val = tile[lo][hi];
            int i = hi * 256 + logrp * 16 + lo;
            obase[sigma16(i)] = val;                   // coalesced scatter
        }
    } else {
        float acc[16];
        #pragma unroll
        for (int q = 0; q < 16; q++) acc[q] = 0.f;
        for (int it = 0; it < 16; it++) {
            int hi = it * 16 + wid * 2 + (lane >> 4);
            int lo = lane & 15;
            float2 val = tile[lo][hi];
            int i = hi * 256 + logrp * 16 + lo;
            int j = sigma16(i);
            float p = val.x * val.x + val.y * val.y;
            #pragma unroll
            for (int q = 0; q < 16; q++) {
                unsigned sgn = ((unsigned)(j >> (15 - q)) & 1u) << 31;
                acc[q] += __int_as_float(__float_as_int(p) ^ sgn);
            }
        }
        #pragma unroll
        for (int q = 0; q < 16; q++) {
            float a = acc[q];
            #pragma unroll
            for (int o = 16; o; o >>= 1) a += __shfl_down_sync(0xffffffffu, a, o);
            if (lane == 0) wsum[wid][q] = a;
        }
        __syncthreads();
        if (tid < 16) {
            float s = 0.f;
            #pragma unroll
            for (int ww = 0; ww < 8; ww++) s += wsum[ww][tid];
            part[(b * 16 + logrp) * 16 + tid] = s;     // deterministic partials
        }
    }
}

// Final deterministic reduction of partials -> out[b][q]
__global__ __launch_bounds__(256)
void k_reduce(const float* __restrict__ part, float* __restrict__ out) {
    int idx = blockIdx.x * 256 + threadIdx.x;          // < 2048
    int b = idx >> 4, q = idx & 15;
    float s = 0.f;
    #pragma unroll
    for (int gp = 0; gp < 16; gp++) s += part[(b * 16 + gp) * 16 + q];
    out[idx] = s;
}

// ---------------------------------------------------------------------------
extern "C" void kernel_launch(void* const* d_in, const int* in_sizes, int n_in,
                              void* d_out, int out_size) {
    const float* x = (const float*)d_in[0];
    const float* w = (const float*)d_in[1];
    if (n_in >= 2 && in_sizes[0] == 192) { const float* t = x; x = w; w = t; }
    float* out = (float*)d_out;

    float2 *s0, *s1; float* part;
    cudaGetSymbolAddress((void**)&s0, g_state0);
    cudaGetSymbolAddress((void**)&s1, g_state1);
    cudaGetSymbolAddress((void**)&part, g_partial);

    k_init<<<BATCH, 256>>>(x, w, s0);

    k_low <<<dim3(32, BATCH), 256>>>(x, w, 1, s0);
    k_high<false><<<dim3(16, BATCH), 256>>>(x, w, 1, s0, s1, nullptr);

    k_low <<<dim3(32, BATCH), 256>>>(x, w, 2, s1);
    k_high<false><<<dim3(16, BATCH), 256>>>(x, w, 2, s1, s0, nullptr);

    k_low <<<dim3(32, BATCH), 256>>>(x, w, 3, s0);
    k_high<true> <<<dim3(16, BATCH), 256>>>(x, w, 3, s0, nullptr, part);

    k_reduce<<<8, 256>>>(part, out);
}